// round 1
// baseline (speedup 1.0000x reference)
#include <cuda_runtime.h>
#include <cuda_bf16.h>

// RoIAlign (torchvision semantics, aligned=True, sampling_ratio=2)
// x:     [B=8, C=256, H=128, W=128] fp32
// boxes: [B=8, N=64, 4] fp32  (x1,y1,x2,y2)
// out:   [B, N, C, 6, 6] fp32
//
// Mapping: one thread computes 4 channels (c, c+64, c+128, c+192) for one
// (b, n, oh, ow). Coordinates/weights are channel-independent, so they're
// computed once per thread; the 16 feature loads per sample point are
// independent -> high MLP. Consecutive threads vary (ow, oh) fastest so
// gathers have spatial locality in L1/L2 and stores are coalesced.

#define B_    8
#define N_    64
#define C_    256
#define H_    128
#define W_    128
#define OUT_H 6
#define OUT_W 6
#define CPT   4            // channels per thread
#define CQ    (C_ / CPT)   // 64 channel-quarters
#define HW    (H_ * W_)

__global__ void __launch_bounds__(256)
roi_align_kernel(const float* __restrict__ x,
                 const float* __restrict__ boxes,
                 float* __restrict__ out)
{
    const int TOTAL = B_ * N_ * CQ * OUT_H * OUT_W;
    int idx = blockIdx.x * blockDim.x + threadIdx.x;
    if (idx >= TOTAL) return;

    int ow = idx % OUT_W;
    int t  = idx / OUT_W;
    int oh = t % OUT_H;  t /= OUT_H;
    int cq = t % CQ;     t /= CQ;
    int n  = t % N_;
    int b  = t / N_;

    // box (aligned=True: half-pixel offset)
    const float* box = boxes + (b * N_ + n) * 4;
    float x1 = __ldg(box + 0) - 0.5f;
    float y1 = __ldg(box + 1) - 0.5f;
    float x2 = __ldg(box + 2) - 0.5f;
    float y2 = __ldg(box + 3) - 0.5f;
    float bin_w = (x2 - x1) * (1.0f / OUT_W);
    float bin_h = (y2 - y1) * (1.0f / OUT_H);

    // Precompute 1-D interpolation data for the 2 y-samples and 2 x-samples.
    int   yl[2], yh[2], xl[2], xh[2];
    float wy0[2], wy1[2], wx0[2], wx1[2];

    #pragma unroll
    for (int i = 0; i < 2; i++) {
        // y axis
        float yy = y1 + ((float)oh + ((float)i + 0.5f) * 0.5f) * bin_h;
        bool  vy = (yy >= -1.0f) && (yy <= (float)H_);
        float cy = fmaxf(yy, 0.0f);
        int   lo = (int)floorf(cy);
        bool  ey = (lo >= H_ - 1);
        yl[i] = ey ? (H_ - 1) : lo;
        yh[i] = ey ? (H_ - 1) : (lo + 1);
        float fy = ey ? 0.0f : (cy - (float)lo);
        wy1[i] = vy ? fy : 0.0f;
        wy0[i] = vy ? (1.0f - fy) : 0.0f;

        // x axis
        float xx = x1 + ((float)ow + ((float)i + 0.5f) * 0.5f) * bin_w;
        bool  vx = (xx >= -1.0f) && (xx <= (float)W_);
        float cx = fmaxf(xx, 0.0f);
        int   lx = (int)floorf(cx);
        bool  ex = (lx >= W_ - 1);
        xl[i] = ex ? (W_ - 1) : lx;
        xh[i] = ex ? (W_ - 1) : (lx + 1);
        float fx = ex ? 0.0f : (cx - (float)lx);
        wx1[i] = vx ? fx : 0.0f;
        wx0[i] = vx ? (1.0f - fx) : 0.0f;
    }

    const float* base = x + ((size_t)b * C_ + cq) * HW;

    float acc[CPT];
    #pragma unroll
    for (int k = 0; k < CPT; k++) acc[k] = 0.0f;

    #pragma unroll
    for (int iy = 0; iy < 2; iy++) {
        #pragma unroll
        for (int ix = 0; ix < 2; ix++) {
            int o00 = yl[iy] * W_ + xl[ix];
            int o01 = yl[iy] * W_ + xh[ix];
            int o10 = yh[iy] * W_ + xl[ix];
            int o11 = yh[iy] * W_ + xh[ix];
            float w00 = wy0[iy] * wx0[ix];
            float w01 = wy0[iy] * wx1[ix];
            float w10 = wy1[iy] * wx0[ix];
            float w11 = wy1[iy] * wx1[ix];
            #pragma unroll
            for (int k = 0; k < CPT; k++) {
                const float* f = base + (size_t)k * CQ * HW;
                float v00 = __ldg(f + o00);
                float v01 = __ldg(f + o01);
                float v10 = __ldg(f + o10);
                float v11 = __ldg(f + o11);
                acc[k] += w00 * v00 + w01 * v01 + w10 * v10 + w11 * v11;
            }
        }
    }

    // out index: ((b*N + n)*C + c)*36 + oh*6 + ow, with c = cq + k*CQ
    size_t obase = ((size_t)(b * N_ + n) * C_ + cq) * (OUT_H * OUT_W)
                 + oh * OUT_W + ow;
    #pragma unroll
    for (int k = 0; k < CPT; k++) {
        out[obase + (size_t)k * CQ * (OUT_H * OUT_W)] = acc[k] * 0.25f;
    }
}

extern "C" void kernel_launch(void* const* d_in, const int* in_sizes, int n_in,
                              void* d_out, int out_size)
{
    const float* x     = (const float*)d_in[0];
    const float* boxes = (const float*)d_in[1];
    float*       out   = (float*)d_out;

    const int total  = B_ * N_ * CQ * OUT_H * OUT_W;   // 1,179,648 threads
    const int tpb    = 256;
    const int blocks = (total + tpb - 1) / tpb;
    roi_align_kernel<<<blocks, tpb>>>(x, boxes, out);
}

// round 2
// speedup vs baseline: 1.1396x; 1.1396x over previous
#include <cuda_runtime.h>
#include <cuda_fp16.h>

// RoIAlign (torchvision aligned=True, sampling_ratio=2) — two-pass:
//  1) transpose x [B,C,H,W] f32 -> g_xt [B,H,W,C] f16 (channels contiguous)
//  2) gather: warp per (b,n,pos), lanes span channels -> coalesced 128B loads;
//     smem-staged transpose for coalesced f32 output stores.

#define B_    8
#define N_    64
#define C_    256
#define H_    128
#define W_    128
#define HW_   (H_ * W_)
#define OUT_H 6
#define OUT_W 6
#define NPOS  36

// 8 * 16384 * 256 halves = 64 MB scratch (allowed: __device__ global)
__device__ __half g_xt[(size_t)B_ * HW_ * C_];

// ---------------------------------------------------------------------------
// Pass 1: transpose [C, HW] f32 tile -> [HW, C] f16.
// Tile: 64 channels x 32 spatial. Reads coalesced along spatial, writes
// coalesced along channel (half2).
// ---------------------------------------------------------------------------
__global__ void __launch_bounds__(256)
transpose_kernel(const float* __restrict__ x)
{
    __shared__ float sm[64][33];   // +1 pad

    const int b  = blockIdx.z;
    const int c0 = blockIdx.y * 64;
    const int s0 = blockIdx.x * 32;
    const int tid = threadIdx.x;
    const int tx = tid & 31;
    const int ty = tid >> 5;       // 0..7

    const float* src = x + ((size_t)b * C_ + c0) * HW_ + s0;
    #pragma unroll
    for (int r = 0; r < 8; r++) {
        int cl = ty + 8 * r;
        sm[cl][tx] = src[(size_t)cl * HW_ + tx];
    }
    __syncthreads();

    __half2* dst = (__half2*)g_xt;
    const size_t dbase = ((size_t)b * HW_ + s0) * (C_ / 2) + (c0 >> 1) + tx;
    #pragma unroll
    for (int r = 0; r < 4; r++) {
        int sl = ty + 8 * r;
        float v0 = sm[2 * tx + 0][sl];
        float v1 = sm[2 * tx + 1][sl];
        dst[dbase + (size_t)sl * (C_ / 2)] = __floats2half2_rn(v0, v1);
    }
}

// ---------------------------------------------------------------------------
// Pass 2: gather. Block = one (b,n). 8 warps; warp handles output positions
// pos = w, w+8, ... Each lane covers channel pairs c = 2*lane + 64*k (k=0..3)
// so every corner fetch is a coalesced 128B half2 load per k.
// Results staged in smem tile[pos][c] (row stride 258: STS.64 conflict-free),
// then written out fully coalesced in [c][pos] order.
// ---------------------------------------------------------------------------
__global__ void __launch_bounds__(256)
gather_kernel(const float* __restrict__ boxes, float* __restrict__ out)
{
    __shared__ float tile[NPOS][258];

    const int bn   = blockIdx.x;          // b*64 + n
    const int b    = bn >> 6;
    const int tid  = threadIdx.x;
    const int lane = tid & 31;
    const int w    = tid >> 5;            // warp id 0..7

    const float* box = boxes + bn * 4;
    const float x1 = box[0] - 0.5f;
    const float y1 = box[1] - 0.5f;
    const float x2 = box[2] - 0.5f;
    const float y2 = box[3] - 0.5f;
    const float bw = (x2 - x1) * (1.0f / OUT_W);
    const float bh = (y2 - y1) * (1.0f / OUT_H);

    const __half2* xt = (const __half2*)g_xt + (size_t)b * HW_ * (C_ / 2) + lane;

    for (int pos = w; pos < NPOS; pos += 8) {
        const int oh = pos / 6;
        const int ow = pos - 6 * oh;

        int   yl[2], yh[2], xl[2], xh[2];
        float wy0[2], wy1[2], wx0[2], wx1[2];
        #pragma unroll
        for (int i = 0; i < 2; i++) {
            float yy = y1 + ((float)oh + ((float)i + 0.5f) * 0.5f) * bh;
            bool  vy = (yy >= -1.0f) && (yy <= (float)H_);
            float cy = fmaxf(yy, 0.0f);
            int   lo = (int)floorf(cy);
            bool  ey = (lo >= H_ - 1);
            yl[i] = ey ? (H_ - 1) : lo;
            yh[i] = ey ? (H_ - 1) : (lo + 1);
            float fy = ey ? 0.0f : (cy - (float)lo);
            wy1[i] = vy ? fy : 0.0f;
            wy0[i] = vy ? (1.0f - fy) : 0.0f;

            float xx = x1 + ((float)ow + ((float)i + 0.5f) * 0.5f) * bw;
            bool  vx = (xx >= -1.0f) && (xx <= (float)W_);
            float cx = fmaxf(xx, 0.0f);
            int   lx = (int)floorf(cx);
            bool  ex = (lx >= W_ - 1);
            xl[i] = ex ? (W_ - 1) : lx;
            xh[i] = ex ? (W_ - 1) : (lx + 1);
            float fx = ex ? 0.0f : (cx - (float)lx);
            wx1[i] = vx ? fx : 0.0f;
            wx0[i] = vx ? (1.0f - fx) : 0.0f;
        }

        float2 acc[4];
        #pragma unroll
        for (int k = 0; k < 4; k++) acc[k] = make_float2(0.0f, 0.0f);

        #pragma unroll
        for (int iy = 0; iy < 2; iy++) {
            #pragma unroll
            for (int ix = 0; ix < 2; ix++) {
                const int   cyi[4] = { yl[iy], yl[iy], yh[iy], yh[iy] };
                const int   cxi[4] = { xl[ix], xh[ix], xl[ix], xh[ix] };
                const float cwt[4] = { wy0[iy] * wx0[ix], wy0[iy] * wx1[ix],
                                       wy1[iy] * wx0[ix], wy1[iy] * wx1[ix] };
                #pragma unroll
                for (int c4 = 0; c4 < 4; c4++) {
                    const __half2* p = xt + (size_t)(cyi[c4] * W_ + cxi[c4]) * (C_ / 2);
                    const float wgt = cwt[c4];
                    #pragma unroll
                    for (int k = 0; k < 4; k++) {
                        float2 f = __half22float2(p[32 * k]);
                        acc[k].x += wgt * f.x;
                        acc[k].y += wgt * f.y;
                    }
                }
            }
        }

        float2* row = (float2*)&tile[pos][0];   // row base even -> 8B aligned
        #pragma unroll
        for (int k = 0; k < 4; k++) {
            row[lane + 32 * k] = make_float2(acc[k].x * 0.25f, acc[k].y * 0.25f);
        }
    }
    __syncthreads();

    // Write out in output-linear order: e = c*36 + pos, fully coalesced.
    float* obase = out + (size_t)bn * (C_ * NPOS);
    #pragma unroll
    for (int i = 0; i < NPOS; i++) {
        int e   = i * 256 + tid;
        int c   = e / 36;
        int pos = e - 36 * c;
        obase[e] = tile[pos][c];
    }
}

extern "C" void kernel_launch(void* const* d_in, const int* in_sizes, int n_in,
                              void* d_out, int out_size)
{
    const float* x     = (const float*)d_in[0];
    const float* boxes = (const float*)d_in[1];
    float*       out   = (float*)d_out;

    dim3 tgrid(HW_ / 32, C_ / 64, B_);      // 512 x 4 x 8
    transpose_kernel<<<tgrid, 256>>>(x);
    gather_kernel<<<B_ * N_, 256>>>(boxes, out);
}

// round 4
// speedup vs baseline: 1.2951x; 1.1364x over previous
#include <cuda_runtime.h>
#include <cuda_fp16.h>

// RoIAlign (torchvision aligned=True, sampling_ratio=2) — two-pass:
//  1) transpose x [B,C,H,W] f32 -> g_xt [B,H,W,C] f16 (channels contiguous)
//  2) gather: block = (bn, channel-half). Warp per output position group,
//     lanes span channels -> coalesced loads; smem-staged transpose for
//     coalesced f32 output stores. Grid 1024 for full SM residency.

#define B_    8
#define N_    64
#define C_    256
#define H_    128
#define W_    128
#define HW_   (H_ * W_)
#define OUT_H 6
#define OUT_W 6
#define NPOS  36
#define CH_   128            // channels per gather block
#define CH2_  (CH_ / 2)      // 64 half2 per block

// 8 * 16384 * 256 halves = 64 MB scratch (__device__ global: allowed)
__device__ __half g_xt[(size_t)B_ * HW_ * C_];

// ---------------------------------------------------------------------------
// Pass 1: transpose [C, HW] f32 tile -> [HW, C] f16. DRAM-bound (~6.2 TB/s).
// ---------------------------------------------------------------------------
__global__ void __launch_bounds__(256)
transpose_kernel(const float* __restrict__ x)
{
    __shared__ float sm[64][33];

    const int b  = blockIdx.z;
    const int c0 = blockIdx.y * 64;
    const int s0 = blockIdx.x * 32;
    const int tid = threadIdx.x;
    const int tx = tid & 31;
    const int ty = tid >> 5;

    const float* src = x + ((size_t)b * C_ + c0) * HW_ + s0;
    #pragma unroll
    for (int r = 0; r < 8; r++) {
        int cl = ty + 8 * r;
        sm[cl][tx] = src[(size_t)cl * HW_ + tx];
    }
    __syncthreads();

    __half2* dst = (__half2*)g_xt;
    const size_t dbase = ((size_t)b * HW_ + s0) * (C_ / 2) + (c0 >> 1) + tx;
    #pragma unroll
    for (int r = 0; r < 4; r++) {
        int sl = ty + 8 * r;
        float v0 = sm[2 * tx + 0][sl];
        float v1 = sm[2 * tx + 1][sl];
        dst[dbase + (size_t)sl * (C_ / 2)] = __floats2half2_rn(v0, v1);
    }
}

// ---------------------------------------------------------------------------
// Pass 2: gather. blockIdx.x = bn*2 + ch. 8 warps; warp w handles positions
// w, w+8, ... Lanes cover half2 channel pairs (lane + 32k, k=0..1) within the
// 128-channel slab. Output staged in smem tile[pos][clocal], written out
// fully coalesced (block's output slab is contiguous: 128ch x 36pos).
// ---------------------------------------------------------------------------
__global__ void __launch_bounds__(256, 6)
gather_kernel(const float* __restrict__ boxes, float* __restrict__ out)
{
    __shared__ float tile[NPOS][CH_ + 2];   // row stride 130 floats

    const int blk  = blockIdx.x;
    const int bn   = blk >> 1;            // b*64 + n
    const int ch   = blk & 1;             // channel half
    const int b    = bn >> 6;
    const int tid  = threadIdx.x;
    const int lane = tid & 31;
    const int w    = tid >> 5;

    const float* box = boxes + bn * 4;
    const float x1 = __ldg(box + 0) - 0.5f;
    const float y1 = __ldg(box + 1) - 0.5f;
    const float x2 = __ldg(box + 2) - 0.5f;
    const float y2 = __ldg(box + 3) - 0.5f;
    const float bw = (x2 - x1) * (1.0f / OUT_W);
    const float bh = (y2 - y1) * (1.0f / OUT_H);

    const __half2* xt = (const __half2*)g_xt
                      + (size_t)b * HW_ * (C_ / 2) + ch * CH2_ + lane;

    for (int pos = w; pos < NPOS; pos += 8) {
        const int oh = pos / 6;
        const int ow = pos - 6 * oh;

        int   yl[2], yh[2], xl[2], xh[2];
        float wy0[2], wy1[2], wx0[2], wx1[2];
        #pragma unroll
        for (int i = 0; i < 2; i++) {
            float yy = y1 + ((float)oh + ((float)i + 0.5f) * 0.5f) * bh;
            bool  vy = (yy >= -1.0f) && (yy <= (float)H_);
            float cy = fmaxf(yy, 0.0f);
            int   lo = (int)floorf(cy);
            bool  ey = (lo >= H_ - 1);
            yl[i] = ey ? (H_ - 1) : lo;
            yh[i] = ey ? (H_ - 1) : (lo + 1);
            float fy = ey ? 0.0f : (cy - (float)lo);
            wy1[i] = vy ? fy : 0.0f;
            wy0[i] = vy ? (1.0f - fy) : 0.0f;

            float xx = x1 + ((float)ow + ((float)i + 0.5f) * 0.5f) * bw;
            bool  vx = (xx >= -1.0f) && (xx <= (float)W_);
            float cx = fmaxf(xx, 0.0f);
            int   lx = (int)floorf(cx);
            bool  ex = (lx >= W_ - 1);
            xl[i] = ex ? (W_ - 1) : lx;
            xh[i] = ex ? (W_ - 1) : (lx + 1);
            float fx = ex ? 0.0f : (cx - (float)lx);
            wx1[i] = vx ? fx : 0.0f;
            wx0[i] = vx ? (1.0f - fx) : 0.0f;
        }

        float2 acc[2];
        #pragma unroll
        for (int k = 0; k < 2; k++) acc[k] = make_float2(0.0f, 0.0f);

        #pragma unroll
        for (int iy = 0; iy < 2; iy++) {
            #pragma unroll
            for (int ix = 0; ix < 2; ix++) {
                const int   cyi[4] = { yl[iy], yl[iy], yh[iy], yh[iy] };
                const int   cxi[4] = { xl[ix], xh[ix], xl[ix], xh[ix] };
                const float cwt[4] = { wy0[iy] * wx0[ix], wy0[iy] * wx1[ix],
                                       wy1[iy] * wx0[ix], wy1[iy] * wx1[ix] };
                #pragma unroll
                for (int c4 = 0; c4 < 4; c4++) {
                    const __half2* p = xt + (size_t)(cyi[c4] * W_ + cxi[c4]) * (C_ / 2);
                    const float wgt = cwt[c4];
                    #pragma unroll
                    for (int k = 0; k < 2; k++) {
                        float2 f = __half22float2(p[32 * k]);
                        acc[k].x += wgt * f.x;
                        acc[k].y += wgt * f.y;
                    }
                }
            }
        }

        float2* row = (float2*)&tile[pos][0];   // row base even -> 8B aligned
        #pragma unroll
        for (int k = 0; k < 2; k++) {
            row[lane + 32 * k] = make_float2(acc[k].x * 0.25f, acc[k].y * 0.25f);
        }
    }
    __syncthreads();

    // Block's output slab: channels [ch*128, ch*128+128), all 36 pos ->
    // contiguous 4608 floats. 18 fully-coalesced stores per thread.
    float* obase = out + (size_t)bn * (C_ * NPOS) + (size_t)ch * CH_ * NPOS;
    #pragma unroll
    for (int i = 0; i < 18; i++) {
        int e   = i * 256 + tid;
        int c   = e / 36;
        int pos = e - 36 * c;
        obase[e] = tile[pos][c];
    }
}

extern "C" void kernel_launch(void* const* d_in, const int* in_sizes, int n_in,
                              void* d_out, int out_size)
{
    const float* x     = (const float*)d_in[0];
    const float* boxes = (const float*)d_in[1];
    float*       out   = (float*)d_out;

    dim3 tgrid(HW_ / 32, C_ / 64, B_);      // 512 x 4 x 8
    transpose_kernel<<<tgrid, 256>>>(x);
    gather_kernel<<<B_ * N_ * 2, 256>>>(boxes, out);
}